// round 10
// baseline (speedup 1.0000x reference)
#include <cuda_runtime.h>
#include <cuda_fp16.h>

#define NN 50000
#define EE 1600000
#define SCAN_B 256
#define NBLK ((NN + SCAN_B - 1) / SCAN_B)   // 196

// Scratch (device globals; zero-initialized at module load)
__device__ __align__(16) float4 g_h [NN * 32];     // h = (1+eps)*x + agg
__device__ __align__(16) float4 g_h1[NN * 32];     // h @ W1 + b1
__device__ float g_sum[128];
__device__ float g_sumsq[128];
__device__ __align__(16) __half g_ch[125 * 128];   // combo table in fp16
__device__ __align__(16) uint2 g_xh[NN * 32];      // x in fp16
__device__ int  g_deg[NN];                         // zeroed by agg_kernel after use
__device__ int  g_off[NN];
__device__ int  g_cur[NN];
__device__ int  g_bsum[NBLK];
__device__ int  g_boff[NBLK];
__device__ int  g_scan_done;                       // reset by fused_setup each call
__device__ volatile int g_ready;                   // reset by fused_setup each call
__device__ int  g_csr[EE];                         // packed (src<<7)|code, grouped by dst

// ---------------------------------------------------------------------------
// Fused setup: convert x -> fp16, build fp16 combo table, histogram dst,
// reset single-pass-scan flags. NN*32 == EE == 1.6M, one grid covers all.
// ---------------------------------------------------------------------------
__global__ void fused_setup(const float4* __restrict__ x4,
                            const float*  __restrict__ be,
                            const int*    __restrict__ dst) {
    int i = blockIdx.x * blockDim.x + threadIdx.x;
    if (i == 0) { g_scan_done = 0; g_ready = 0; }
    if (i < NN * 32) {
        float4 v = x4[i];
        __half2 lo = __float22half2_rn(make_float2(v.x, v.y));
        __half2 hi = __float22half2_rn(make_float2(v.z, v.w));
        uint2 p;
        p.x = *(unsigned*)&lo;
        p.y = *(unsigned*)&hi;
        g_xh[i] = p;
    }
    if (i < 125 * 128) {
        int c = i >> 7, t = i & 127;
        float s = be[(c / 25) * 128 + t]
                + be[(5 + (c / 5) % 5) * 128 + t]
                + be[(10 + c % 5) * 128 + t];
        g_ch[i] = __float2half_rn(s);
    }
    if (i < EE) atomicAdd(&g_deg[dst[i]], 1);
}

// ---------------------------------------------------------------------------
// Single-pass chip-wide exclusive scan of g_deg -> g_off / g_cur.
// 196 blocks all co-resident (148 SMs) so the last-block spin cannot deadlock.
// Also zeroes the BN stat accumulators (block 0).
// ---------------------------------------------------------------------------
__global__ void scan_kernel() {
    __shared__ int ws[8];
    __shared__ int sh2[SCAN_B];
    __shared__ bool is_last;
    int t = threadIdx.x, lane = t & 31, w = t >> 5, b = blockIdx.x;

    if (b == 0 && t < 128) { g_sum[t] = 0.f; g_sumsq[t] = 0.f; }

    int i = b * SCAN_B + t;
    int v = (i < NN) ? g_deg[i] : 0;

    int s = v;
#pragma unroll
    for (int o = 1; o < 32; o <<= 1) {
        int u = __shfl_up_sync(0xffffffffu, s, o);
        if (lane >= o) s += u;
    }
    if (lane == 31) ws[w] = s;
    __syncthreads();
    if (t < 8) {
        int a = ws[t];
#pragma unroll
        for (int o = 1; o < 8; o <<= 1) {
            int u = __shfl_up_sync(0xffu, a, o);
            if (t >= o) a += u;
        }
        ws[t] = a;
    }
    __syncthreads();

    if (t == 0) {
        g_bsum[b] = ws[7];
        __threadfence();
        int done = atomicAdd(&g_scan_done, 1);
        is_last = (done == NBLK - 1);
    }
    __syncthreads();

    if (is_last) {
        int val = (t < NBLK) ? g_bsum[t] : 0;
        sh2[t] = val;
        __syncthreads();
        for (int o = 1; o < SCAN_B; o <<= 1) {
            int u = (t >= o) ? sh2[t - o] : 0;
            __syncthreads();
            sh2[t] += u;
            __syncthreads();
        }
        if (t < NBLK) g_boff[t] = sh2[t] - val;
        __threadfence();
        __syncthreads();
        if (t == 0) g_ready = 1;
    }

    if (t == 0) { while (g_ready == 0) { } }
    __syncthreads();
    __threadfence();

    int ex = s - v + (w ? ws[w - 1] : 0) + g_boff[b];
    if (i < NN) { g_off[i] = ex; g_cur[i] = ex; }
}

__global__ void scatter_kernel(const int* __restrict__ src,
                               const int* __restrict__ dst,
                               const int* __restrict__ ea) {
    int e = blockIdx.x * blockDim.x + threadIdx.x;
    if (e >= EE) return;
    int d = dst[e];
    int code = (ea[e * 3 + 0] * 5 + ea[e * 3 + 1]) * 5 + ea[e * 3 + 2];
    int pos = atomicAdd(&g_cur[d], 1);
    g_csr[pos] = (src[e] << 7) | code;   // src < 2^16, code < 2^7
}

// ---------------------------------------------------------------------------
// Aggregation: one warp per dst node. Software-pipelined: per 8-edge group,
// first load 8 CSR words, then issue ALL 16 gathers into live register
// arrays (forces MLP=16), then consume. fp16 data, fp32 accumulation.
// ---------------------------------------------------------------------------
__global__ void __launch_bounds__(256) agg_kernel(const float4* __restrict__ x4,
                                                  const float*  __restrict__ eps) {
    int gt = blockIdx.x * blockDim.x + threadIdx.x;
    int v = gt >> 5;
    if (v >= NN) return;
    int lane = gt & 31;

    int start = g_off[v];
    int deg   = g_deg[v];
    if (lane == 0) g_deg[v] = 0;   // reset for next kernel_launch call

    const __half2 z = __float2half2_rn(0.f);
    float4 acc = make_float4(0, 0, 0, 0);

    int i = 0;
    for (; i + 8 <= deg; i += 8) {
        int p[8];
#pragma unroll
        for (int j = 0; j < 8; j++) p[j] = g_csr[start + i + j];

        uint2 xv[8], cv[8];
#pragma unroll
        for (int j = 0; j < 8; j++) {
            xv[j] = g_xh[(p[j] >> 7) * 32 + lane];
            cv[j] = ((const uint2*)g_ch)[(p[j] & 127) * 32 + lane];
        }

#pragma unroll
        for (int j = 0; j < 8; j++) {
            __half2 m0 = __hmax2(__hadd2(*(__half2*)&xv[j].x, *(__half2*)&cv[j].x), z);
            __half2 m1 = __hmax2(__hadd2(*(__half2*)&xv[j].y, *(__half2*)&cv[j].y), z);
            float2 f0 = __half22float2(m0);
            float2 f1 = __half22float2(m1);
            acc.x += f0.x; acc.y += f0.y; acc.z += f1.x; acc.w += f1.y;
        }
    }
    // Remainder (same pipelined shape, variable count)
    if (i < deg) {
        int n = deg - i;   // 1..7
        int p[7];
        uint2 xv[7], cv[7];
#pragma unroll
        for (int j = 0; j < 7; j++) if (j < n) p[j] = g_csr[start + i + j];
#pragma unroll
        for (int j = 0; j < 7; j++) if (j < n) {
            xv[j] = g_xh[(p[j] >> 7) * 32 + lane];
            cv[j] = ((const uint2*)g_ch)[(p[j] & 127) * 32 + lane];
        }
#pragma unroll
        for (int j = 0; j < 7; j++) if (j < n) {
            __half2 m0 = __hmax2(__hadd2(*(__half2*)&xv[j].x, *(__half2*)&cv[j].x), z);
            __half2 m1 = __hmax2(__hadd2(*(__half2*)&xv[j].y, *(__half2*)&cv[j].y), z);
            float2 f0 = __half22float2(m0);
            float2 f1 = __half22float2(m1);
            acc.x += f0.x; acc.y += f0.y; acc.z += f1.x; acc.w += f1.y;
        }
    }

    float c = 1.0f + *eps;
    float4 xv = x4[v * 32 + lane];
    float4 h;
    h.x = fmaf(c, xv.x, acc.x);
    h.y = fmaf(c, xv.y, acc.y);
    h.z = fmaf(c, xv.z, acc.z);
    h.w = fmaf(c, xv.w, acc.w);
    g_h[v * 32 + lane] = h;
}

// ---------------------------------------------------------------------------
// GEMM via fma.rn.f32x2, even/odd-k packed accumulators (unchanged).
// ---------------------------------------------------------------------------
#define WT_PITCH 132
#define WT_FLOATS (128 * WT_PITCH)
#define XS_OFF_B  (WT_FLOATS * 4)
#define GEMM_SMEM (XS_OFF_B + 64 * 128 * 4)

__device__ __forceinline__ float2 unpk(unsigned long long v) {
    float2 r;
    asm("mov.b64 {%0, %1}, %2;" : "=f"(r.x), "=f"(r.y) : "l"(v));
    return r;
}

template <int PASS>
__global__ __launch_bounds__(128)
void gemm_kernel(const float* __restrict__ Wg,
                 const float* __restrict__ bias,
                 float*       __restrict__ outp,
                 const float* __restrict__ gamma,
                 const float* __restrict__ beta) {
    extern __shared__ float sh[];
    __shared__ __align__(16) float ssum[128];
    __shared__ __align__(16) float ssq[128];
    __shared__ __align__(16) float sa[128];
    __shared__ __align__(16) float sb[128];

    const int t    = threadIdx.x;
    const int lane = t & 31;
    const int wrp  = t >> 5;

    if (PASS == 1) { ssum[t] = 0.f; ssq[t] = 0.f; }
    if (PASS == 2) {
        const float inv = 1.0f / (float)NN;
        float mean = g_sum[t] * inv;
        float var  = g_sumsq[t] * inv - mean * mean;
        float s = gamma[t] * rsqrtf(var + 1e-5f);
        sa[t] = s;
        sb[t] = beta[t] - mean * s;
    }
    __syncthreads();

    // Stage W transposed: Wt[c][k] = W[k][c], pitch 132
    {
        const int c = t;
        for (int g = 0; g < 32; g++) {
            int k0 = g * 4;
            float w0 = Wg[(k0 + 0) * 128 + c];
            float w1 = Wg[(k0 + 1) * 128 + c];
            float w2 = Wg[(k0 + 2) * 128 + c];
            float w3 = Wg[(k0 + 3) * 128 + c];
            *(float4*)&sh[c * WT_PITCH + k0] = make_float4(w0, w1, w2, w3);
        }
    }

    const float4* in4 = (PASS == 1) ? (const float4*)g_h : (const float4*)g_h1;
    float* xs = sh + WT_FLOATS;
    const int rowbase = blockIdx.x * 64;
#pragma unroll
    for (int j = 0; j < 16; j++) {
        int p = t + j * 128;
        int row = p >> 5, cp = p & 31;
        int gr = rowbase + row;
        float4 v = make_float4(0, 0, 0, 0);
        if (gr < NN) v = in4[gr * 32 + cp];
        if (PASS == 2) {
            float4 a = *(const float4*)&sa[cp * 4];
            float4 b = *(const float4*)&sb[cp * 4];
            v.x = fmaxf(fmaf(v.x, a.x, b.x), 0.f);
            v.y = fmaxf(fmaf(v.y, a.y, b.y), 0.f);
            v.z = fmaxf(fmaf(v.z, a.z, b.z), 0.f);
            v.w = fmaxf(fmaf(v.w, a.w, b.w), 0.f);
        }
        *(float4*)&xs[row * 128 + cp * 4] = v;
    }
    __syncthreads();

    float* out_f = (PASS == 1) ? (float*)g_h1 : outp;

    float bv[4];
#pragma unroll
    for (int cc = 0; cc < 4; cc++) bv[cc] = bias[lane + 32 * cc];

    const unsigned shb = (unsigned)__cvta_generic_to_shared(sh);
    unsigned wb[4];
#pragma unroll
    for (int cc = 0; cc < 4; cc++) wb[cc] = shb + (unsigned)((lane + 32 * cc) * WT_PITCH) * 4u;
    const unsigned xsb = shb + XS_OFF_B;

    float ts[4] = {0, 0, 0, 0};
    float tq[4] = {0, 0, 0, 0};

    for (int half = 0; half < 2; half++) {
        const int r0 = half * 32 + wrp * 8;
        unsigned xr[8];
#pragma unroll
        for (int r = 0; r < 8; r++) xr[r] = xsb + (unsigned)((r0 + r) * 128) * 4u;

        unsigned long long acc[8][4];
#pragma unroll
        for (int r = 0; r < 8; r++)
#pragma unroll
            for (int cc = 0; cc < 4; cc++) acc[r][cc] = 0ULL;

#pragma unroll 4
        for (int k = 0; k < 128; k += 4) {
            unsigned long long w01[4], w23[4];
#pragma unroll
            for (int cc = 0; cc < 4; cc++)
                asm("ld.shared.v2.b64 {%0, %1}, [%2];"
                    : "=l"(w01[cc]), "=l"(w23[cc]) : "r"(wb[cc] + (unsigned)(k * 4)));
#pragma unroll
            for (int r = 0; r < 8; r++) {
                unsigned long long x01, x23;
                asm("ld.shared.v2.b64 {%0, %1}, [%2];"
                    : "=l"(x01), "=l"(x23) : "r"(xr[r] + (unsigned)(k * 4)));
#pragma unroll
                for (int cc = 0; cc < 4; cc++) {
                    asm("fma.rn.f32x2 %0, %1, %2, %0;" : "+l"(acc[r][cc]) : "l"(x01), "l"(w01[cc]));
                    asm("fma.rn.f32x2 %0, %1, %2, %0;" : "+l"(acc[r][cc]) : "l"(x23), "l"(w23[cc]));
                }
            }
        }

#pragma unroll
        for (int r = 0; r < 8; r++) {
            int gr = rowbase + r0 + r;
            if (gr < NN) {
#pragma unroll
                for (int cc = 0; cc < 4; cc++) {
                    float2 p = unpk(acc[r][cc]);
                    float o = p.x + p.y + bv[cc];
                    out_f[gr * 128 + lane + 32 * cc] = o;
                    if (PASS == 1) { ts[cc] += o; tq[cc] += o * o; }
                }
            }
        }
    }

    if (PASS == 1) {
#pragma unroll
        for (int cc = 0; cc < 4; cc++) {
            atomicAdd(&ssum[lane + 32 * cc], ts[cc]);
            atomicAdd(&ssq [lane + 32 * cc], tq[cc]);
        }
        __syncthreads();
        atomicAdd(&g_sum[t],   ssum[t]);
        atomicAdd(&g_sumsq[t], ssq[t]);
    }
}

// ---------------------------------------------------------------------------
extern "C" void kernel_launch(void* const* d_in, const int* in_sizes, int n_in,
                              void* d_out, int out_size) {
    const float* x     = (const float*)d_in[0];
    const int*   ea    = (const int*)  d_in[1];
    const int*   src   = (const int*)  d_in[2];
    const int*   dst   = (const int*)  d_in[3];
    const float* bond  = (const float*)d_in[4];
    const float* eps   = (const float*)d_in[5];
    const float* W1    = (const float*)d_in[6];
    const float* b1    = (const float*)d_in[7];
    const float* gamma = (const float*)d_in[8];
    const float* beta  = (const float*)d_in[9];
    const float* W2    = (const float*)d_in[10];
    const float* b2    = (const float*)d_in[11];

    cudaFuncSetAttribute(gemm_kernel<1>, cudaFuncAttributeMaxDynamicSharedMemorySize, GEMM_SMEM);
    cudaFuncSetAttribute(gemm_kernel<2>, cudaFuncAttributeMaxDynamicSharedMemorySize, GEMM_SMEM);

    fused_setup<<<(NN * 32 + 255) / 256, 256>>>((const float4*)x, bond, dst);
    scan_kernel<<<NBLK, SCAN_B>>>();
    scatter_kernel<<<(EE + 255) / 256, 256>>>(src, dst, ea);
    agg_kernel<<<(NN * 32 + 255) / 256, 256>>>((const float4*)x, eps);
    gemm_kernel<1><<<(NN + 63) / 64, 128, GEMM_SMEM>>>(W1, b1, nullptr, nullptr, nullptr);
    gemm_kernel<2><<<(NN + 63) / 64, 128, GEMM_SMEM>>>(W2, b2, (float*)d_out, gamma, beta);
}

// round 11
// speedup vs baseline: 1.5233x; 1.5233x over previous
#include <cuda_runtime.h>
#include <cuda_fp16.h>

#define NN 50000
#define EE 1600000
#define SCAN_B 256
#define NBLK ((NN + SCAN_B - 1) / SCAN_B)   // 196

// Scratch (device globals; zero-initialized at module load)
__device__ __align__(16) float4 g_h [NN * 32];     // h = (1+eps)*x + agg
__device__ __align__(16) float4 g_h1[NN * 32];     // h @ W1 + b1
__device__ float g_sum[128];
__device__ float g_sumsq[128];
__device__ __align__(16) __half g_ch[125 * 128];   // combo table in fp16
__device__ __align__(16) uint2 g_xh[NN * 32];      // x in fp16
__device__ int  g_deg[NN];                         // zeroed by agg_kernel after use
__device__ int  g_off[NN];
__device__ int  g_cur[NN];
__device__ int  g_bsum[NBLK];
__device__ int  g_boff[NBLK];
__device__ int  g_scan_done;                       // reset by fused_setup each call
__device__ volatile int g_ready;                   // reset by fused_setup each call
__device__ int  g_csr[EE];                         // packed (src<<7)|code, grouped by dst

// ---------------------------------------------------------------------------
// Fused setup: convert x -> fp16, build fp16 combo table, histogram dst,
// reset single-pass-scan flags. NN*32 == EE == 1.6M, one grid covers all.
// ---------------------------------------------------------------------------
__global__ void fused_setup(const float4* __restrict__ x4,
                            const float*  __restrict__ be,
                            const int*    __restrict__ dst) {
    int i = blockIdx.x * blockDim.x + threadIdx.x;
    if (i == 0) { g_scan_done = 0; g_ready = 0; }
    if (i < NN * 32) {
        float4 v = x4[i];
        __half2 lo = __float22half2_rn(make_float2(v.x, v.y));
        __half2 hi = __float22half2_rn(make_float2(v.z, v.w));
        uint2 p;
        p.x = *(unsigned*)&lo;
        p.y = *(unsigned*)&hi;
        g_xh[i] = p;
    }
    if (i < 125 * 128) {
        int c = i >> 7, t = i & 127;
        float s = be[(c / 25) * 128 + t]
                + be[(5 + (c / 5) % 5) * 128 + t]
                + be[(10 + c % 5) * 128 + t];
        g_ch[i] = __float2half_rn(s);
    }
    if (i < EE) atomicAdd(&g_deg[dst[i]], 1);
}

// ---------------------------------------------------------------------------
// Single-pass chip-wide exclusive scan of g_deg -> g_off / g_cur.
// 196 blocks all co-resident (148 SMs) so the last-block spin cannot deadlock.
// Also zeroes the BN stat accumulators (block 0).
// ---------------------------------------------------------------------------
__global__ void scan_kernel() {
    __shared__ int ws[8];
    __shared__ int sh2[SCAN_B];
    __shared__ bool is_last;
    int t = threadIdx.x, lane = t & 31, w = t >> 5, b = blockIdx.x;

    if (b == 0 && t < 128) { g_sum[t] = 0.f; g_sumsq[t] = 0.f; }

    int i = b * SCAN_B + t;
    int v = (i < NN) ? g_deg[i] : 0;

    int s = v;
#pragma unroll
    for (int o = 1; o < 32; o <<= 1) {
        int u = __shfl_up_sync(0xffffffffu, s, o);
        if (lane >= o) s += u;
    }
    if (lane == 31) ws[w] = s;
    __syncthreads();
    if (t < 8) {
        int a = ws[t];
#pragma unroll
        for (int o = 1; o < 8; o <<= 1) {
            int u = __shfl_up_sync(0xffu, a, o);
            if (t >= o) a += u;
        }
        ws[t] = a;
    }
    __syncthreads();

    if (t == 0) {
        g_bsum[b] = ws[7];
        __threadfence();
        int done = atomicAdd(&g_scan_done, 1);
        is_last = (done == NBLK - 1);
    }
    __syncthreads();

    if (is_last) {
        int val = (t < NBLK) ? g_bsum[t] : 0;
        sh2[t] = val;
        __syncthreads();
        for (int o = 1; o < SCAN_B; o <<= 1) {
            int u = (t >= o) ? sh2[t - o] : 0;
            __syncthreads();
            sh2[t] += u;
            __syncthreads();
        }
        if (t < NBLK) g_boff[t] = sh2[t] - val;
        __threadfence();
        __syncthreads();
        if (t == 0) g_ready = 1;
    }

    if (t == 0) { while (g_ready == 0) { } }
    __syncthreads();
    __threadfence();

    int ex = s - v + (w ? ws[w - 1] : 0) + g_boff[b];
    if (i < NN) { g_off[i] = ex; g_cur[i] = ex; }
}

__global__ void scatter_kernel(const int* __restrict__ src,
                               const int* __restrict__ dst,
                               const int* __restrict__ ea) {
    int e = blockIdx.x * blockDim.x + threadIdx.x;
    if (e >= EE) return;
    int d = dst[e];
    int code = (ea[e * 3 + 0] * 5 + ea[e * 3 + 1]) * 5 + ea[e * 3 + 2];
    int pos = atomicAdd(&g_cur[d], 1);
    g_csr[pos] = (src[e] << 7) | code;   // src < 2^16, code < 2^7
}

// ---------------------------------------------------------------------------
// Aggregation: TWO nodes per warp (independent latency chains -> high MLP),
// all loads named scalars (no register arrays -> no local spills).
// fp16 gather + fp16 combo, half2 add/ReLU, fp32 accumulation.
// ---------------------------------------------------------------------------
__device__ __forceinline__ void acc_edge(float4& acc, int p, int lane) {
    int s    = p >> 7;
    int code = p & 127;
    uint2 xv = g_xh[s * 32 + lane];
    uint2 cv = ((const uint2*)g_ch)[code * 32 + lane];
    __half2 z = __float2half2_rn(0.f);
    __half2 m0 = __hmax2(__hadd2(*(__half2*)&xv.x, *(__half2*)&cv.x), z);
    __half2 m1 = __hmax2(__hadd2(*(__half2*)&xv.y, *(__half2*)&cv.y), z);
    float2 f0 = __half22float2(m0);
    float2 f1 = __half22float2(m1);
    acc.x += f0.x; acc.y += f0.y; acc.z += f1.x; acc.w += f1.y;
}

__device__ __forceinline__ void hconsume(float4& acc, uint2 xv, uint2 cv) {
    __half2 z = __float2half2_rn(0.f);
    __half2 m0 = __hmax2(__hadd2(*(__half2*)&xv.x, *(__half2*)&cv.x), z);
    __half2 m1 = __hmax2(__hadd2(*(__half2*)&xv.y, *(__half2*)&cv.y), z);
    float2 f0 = __half22float2(m0);
    float2 f1 = __half22float2(m1);
    acc.x += f0.x; acc.y += f0.y; acc.z += f1.x; acc.w += f1.y;
}

__global__ void __launch_bounds__(256) agg_kernel(const float4* __restrict__ x4,
                                                  const float*  __restrict__ eps) {
    int gt   = blockIdx.x * blockDim.x + threadIdx.x;
    int wrp  = gt >> 5;
    int lane = gt & 31;
    int v0   = wrp * 2;
    if (v0 >= NN) return;
    int v1 = v0 + 1;
    bool has1 = (v1 < NN);

    int s0 = g_off[v0];
    int d0 = g_deg[v0];
    int s1 = has1 ? g_off[v1] : 0;
    int d1 = has1 ? g_deg[v1] : 0;
    if (lane == 0) {
        g_deg[v0] = 0;                 // reset for next kernel_launch call
        if (has1) g_deg[v1] = 0;
    }

    const uint2* ch2 = (const uint2*)g_ch;
    float4 a0 = make_float4(0, 0, 0, 0);
    float4 a1 = make_float4(0, 0, 0, 0);

    int i0 = 0, i1 = 0;
    // Fused main loop: 4 edges from each node in flight (8 edges, 16 gathers)
    for (; i0 + 4 <= d0 && i1 + 4 <= d1; i0 += 4, i1 += 4) {
        int pa0 = g_csr[s0 + i0    ];
        int pa1 = g_csr[s0 + i0 + 1];
        int pa2 = g_csr[s0 + i0 + 2];
        int pa3 = g_csr[s0 + i0 + 3];
        int pb0 = g_csr[s1 + i1    ];
        int pb1 = g_csr[s1 + i1 + 1];
        int pb2 = g_csr[s1 + i1 + 2];
        int pb3 = g_csr[s1 + i1 + 3];

        uint2 xa0 = g_xh[(pa0 >> 7) * 32 + lane];
        uint2 xa1 = g_xh[(pa1 >> 7) * 32 + lane];
        uint2 xa2 = g_xh[(pa2 >> 7) * 32 + lane];
        uint2 xa3 = g_xh[(pa3 >> 7) * 32 + lane];
        uint2 xb0 = g_xh[(pb0 >> 7) * 32 + lane];
        uint2 xb1 = g_xh[(pb1 >> 7) * 32 + lane];
        uint2 xb2 = g_xh[(pb2 >> 7) * 32 + lane];
        uint2 xb3 = g_xh[(pb3 >> 7) * 32 + lane];
        uint2 ca0 = ch2[(pa0 & 127) * 32 + lane];
        uint2 ca1 = ch2[(pa1 & 127) * 32 + lane];
        uint2 ca2 = ch2[(pa2 & 127) * 32 + lane];
        uint2 ca3 = ch2[(pa3 & 127) * 32 + lane];
        uint2 cb0 = ch2[(pb0 & 127) * 32 + lane];
        uint2 cb1 = ch2[(pb1 & 127) * 32 + lane];
        uint2 cb2 = ch2[(pb2 & 127) * 32 + lane];
        uint2 cb3 = ch2[(pb3 & 127) * 32 + lane];

        hconsume(a0, xa0, ca0);
        hconsume(a0, xa1, ca1);
        hconsume(a0, xa2, ca2);
        hconsume(a0, xa3, ca3);
        hconsume(a1, xb0, cb0);
        hconsume(a1, xb1, cb1);
        hconsume(a1, xb2, cb2);
        hconsume(a1, xb3, cb3);
    }
    // Tails: simple per-edge loops (no arrays, no spills)
    for (; i0 < d0; i0++) acc_edge(a0, g_csr[s0 + i0], lane);
    for (; i1 < d1; i1++) acc_edge(a1, g_csr[s1 + i1], lane);

    float c = 1.0f + *eps;
    {
        float4 xv = x4[v0 * 32 + lane];
        float4 h;
        h.x = fmaf(c, xv.x, a0.x);
        h.y = fmaf(c, xv.y, a0.y);
        h.z = fmaf(c, xv.z, a0.z);
        h.w = fmaf(c, xv.w, a0.w);
        g_h[v0 * 32 + lane] = h;
    }
    if (has1) {
        float4 xv = x4[v1 * 32 + lane];
        float4 h;
        h.x = fmaf(c, xv.x, a1.x);
        h.y = fmaf(c, xv.y, a1.y);
        h.z = fmaf(c, xv.z, a1.z);
        h.w = fmaf(c, xv.w, a1.w);
        g_h[v1 * 32 + lane] = h;
    }
}

// ---------------------------------------------------------------------------
// GEMM via fma.rn.f32x2, even/odd-k packed accumulators (unchanged).
// ---------------------------------------------------------------------------
#define WT_PITCH 132
#define WT_FLOATS (128 * WT_PITCH)
#define XS_OFF_B  (WT_FLOATS * 4)
#define GEMM_SMEM (XS_OFF_B + 64 * 128 * 4)

__device__ __forceinline__ float2 unpk(unsigned long long v) {
    float2 r;
    asm("mov.b64 {%0, %1}, %2;" : "=f"(r.x), "=f"(r.y) : "l"(v));
    return r;
}

template <int PASS>
__global__ __launch_bounds__(128)
void gemm_kernel(const float* __restrict__ Wg,
                 const float* __restrict__ bias,
                 float*       __restrict__ outp,
                 const float* __restrict__ gamma,
                 const float* __restrict__ beta) {
    extern __shared__ float sh[];
    __shared__ __align__(16) float ssum[128];
    __shared__ __align__(16) float ssq[128];
    __shared__ __align__(16) float sa[128];
    __shared__ __align__(16) float sb[128];

    const int t    = threadIdx.x;
    const int lane = t & 31;
    const int wrp  = t >> 5;

    if (PASS == 1) { ssum[t] = 0.f; ssq[t] = 0.f; }
    if (PASS == 2) {
        const float inv = 1.0f / (float)NN;
        float mean = g_sum[t] * inv;
        float var  = g_sumsq[t] * inv - mean * mean;
        float s = gamma[t] * rsqrtf(var + 1e-5f);
        sa[t] = s;
        sb[t] = beta[t] - mean * s;
    }
    __syncthreads();

    // Stage W transposed: Wt[c][k] = W[k][c], pitch 132
    {
        const int c = t;
        for (int g = 0; g < 32; g++) {
            int k0 = g * 4;
            float w0 = Wg[(k0 + 0) * 128 + c];
            float w1 = Wg[(k0 + 1) * 128 + c];
            float w2 = Wg[(k0 + 2) * 128 + c];
            float w3 = Wg[(k0 + 3) * 128 + c];
            *(float4*)&sh[c * WT_PITCH + k0] = make_float4(w0, w1, w2, w3);
        }
    }

    const float4* in4 = (PASS == 1) ? (const float4*)g_h : (const float4*)g_h1;
    float* xs = sh + WT_FLOATS;
    const int rowbase = blockIdx.x * 64;
#pragma unroll
    for (int j = 0; j < 16; j++) {
        int p = t + j * 128;
        int row = p >> 5, cp = p & 31;
        int gr = rowbase + row;
        float4 v = make_float4(0, 0, 0, 0);
        if (gr < NN) v = in4[gr * 32 + cp];
        if (PASS == 2) {
            float4 a = *(const float4*)&sa[cp * 4];
            float4 b = *(const float4*)&sb[cp * 4];
            v.x = fmaxf(fmaf(v.x, a.x, b.x), 0.f);
            v.y = fmaxf(fmaf(v.y, a.y, b.y), 0.f);
            v.z = fmaxf(fmaf(v.z, a.z, b.z), 0.f);
            v.w = fmaxf(fmaf(v.w, a.w, b.w), 0.f);
        }
        *(float4*)&xs[row * 128 + cp * 4] = v;
    }
    __syncthreads();

    float* out_f = (PASS == 1) ? (float*)g_h1 : outp;

    float bv[4];
#pragma unroll
    for (int cc = 0; cc < 4; cc++) bv[cc] = bias[lane + 32 * cc];

    const unsigned shb = (unsigned)__cvta_generic_to_shared(sh);
    unsigned wb[4];
#pragma unroll
    for (int cc = 0; cc < 4; cc++) wb[cc] = shb + (unsigned)((lane + 32 * cc) * WT_PITCH) * 4u;
    const unsigned xsb = shb + XS_OFF_B;

    float ts[4] = {0, 0, 0, 0};
    float tq[4] = {0, 0, 0, 0};

    for (int half = 0; half < 2; half++) {
        const int r0 = half * 32 + wrp * 8;
        unsigned xr[8];
#pragma unroll
        for (int r = 0; r < 8; r++) xr[r] = xsb + (unsigned)((r0 + r) * 128) * 4u;

        unsigned long long acc[8][4];
#pragma unroll
        for (int r = 0; r < 8; r++)
#pragma unroll
            for (int cc = 0; cc < 4; cc++) acc[r][cc] = 0ULL;

#pragma unroll 4
        for (int k = 0; k < 128; k += 4) {
            unsigned long long w01[4], w23[4];
#pragma unroll
            for (int cc = 0; cc < 4; cc++)
                asm("ld.shared.v2.b64 {%0, %1}, [%2];"
                    : "=l"(w01[cc]), "=l"(w23[cc]) : "r"(wb[cc] + (unsigned)(k * 4)));
#pragma unroll
            for (int r = 0; r < 8; r++) {
                unsigned long long x01, x23;
                asm("ld.shared.v2.b64 {%0, %1}, [%2];"
                    : "=l"(x01), "=l"(x23) : "r"(xr[r] + (unsigned)(k * 4)));
#pragma unroll
                for (int cc = 0; cc < 4; cc++) {
                    asm("fma.rn.f32x2 %0, %1, %2, %0;" : "+l"(acc[r][cc]) : "l"(x01), "l"(w01[cc]));
                    asm("fma.rn.f32x2 %0, %1, %2, %0;" : "+l"(acc[r][cc]) : "l"(x23), "l"(w23[cc]));
                }
            }
        }

#pragma unroll
        for (int r = 0; r < 8; r++) {
            int gr = rowbase + r0 + r;
            if (gr < NN) {
#pragma unroll
                for (int cc = 0; cc < 4; cc++) {
                    float2 p = unpk(acc[r][cc]);
                    float o = p.x + p.y + bv[cc];
                    out_f[gr * 128 + lane + 32 * cc] = o;
                    if (PASS == 1) { ts[cc] += o; tq[cc] += o * o; }
                }
            }
        }
    }

    if (PASS == 1) {
#pragma unroll
        for (int cc = 0; cc < 4; cc++) {
            atomicAdd(&ssum[lane + 32 * cc], ts[cc]);
            atomicAdd(&ssq [lane + 32 * cc], tq[cc]);
        }
        __syncthreads();
        atomicAdd(&g_sum[t],   ssum[t]);
        atomicAdd(&g_sumsq[t], ssq[t]);
    }
}

// ---------------------------------------------------------------------------
extern "C" void kernel_launch(void* const* d_in, const int* in_sizes, int n_in,
                              void* d_out, int out_size) {
    const float* x     = (const float*)d_in[0];
    const int*   ea    = (const int*)  d_in[1];
    const int*   src   = (const int*)  d_in[2];
    const int*   dst   = (const int*)  d_in[3];
    const float* bond  = (const float*)d_in[4];
    const float* eps   = (const float*)d_in[5];
    const float* W1    = (const float*)d_in[6];
    const float* b1    = (const float*)d_in[7];
    const float* gamma = (const float*)d_in[8];
    const float* beta  = (const float*)d_in[9];
    const float* W2    = (const float*)d_in[10];
    const float* b2    = (const float*)d_in[11];

    cudaFuncSetAttribute(gemm_kernel<1>, cudaFuncAttributeMaxDynamicSharedMemorySize, GEMM_SMEM);
    cudaFuncSetAttribute(gemm_kernel<2>, cudaFuncAttributeMaxDynamicSharedMemorySize, GEMM_SMEM);

    fused_setup<<<(NN * 32 + 255) / 256, 256>>>((const float4*)x, bond, dst);
    scan_kernel<<<NBLK, SCAN_B>>>();
    scatter_kernel<<<(EE + 255) / 256, 256>>>(src, dst, ea);
    // 2 nodes per warp -> NN/2 warps -> 8 warps per 256-thread block
    agg_kernel<<<(NN / 2 + 7) / 8, 256>>>((const float4*)x, eps);
    gemm_kernel<1><<<(NN + 63) / 64, 128, GEMM_SMEM>>>(W1, b1, nullptr, nullptr, nullptr);
    gemm_kernel<2><<<(NN + 63) / 64, 128, GEMM_SMEM>>>(W2, b2, (float*)d_out, gamma, beta);
}